// round 6
// baseline (speedup 1.0000x reference)
#include <cuda_runtime.h>
#include <math.h>

// ---------------------------------------------------------------------------
// CausalEdgeAttention — algebraically reduced:
//   out = edge_attr + relu(nc@W1eff + b1) @ Meff + c2
//   nc    = nf[src]+nf[tgt]          (0.5 folded into W1eff = 0.5*n_W1)
//   Meff  = 0.5 * diag(scale) * M,   M = n_W2 @ Wv @ Wo @ Wp
//   c2    = 0.5 * (b2@R2 + bv@R1 + bo@Wp + bp + shift@M)
//   scale = gamma*rsqrt(var+eps), shift = beta - mu*scale (BN stats of h1)
// Edge encoder in the reference is dead code -> skipped.
// Scalar f32x2 pipeline; LDS.128 staging; bias folded into fma-chain C operand.
// ---------------------------------------------------------------------------

#define HDIM 256
#define DDIM 8
#define NBLKA 512

typedef unsigned long long u64;

__device__ __forceinline__ u64 pk(float lo, float hi) {
    u64 r; asm("mov.b64 %0,{%1,%2};" : "=l"(r) : "f"(lo), "f"(hi)); return r;
}
__device__ __forceinline__ void upk(u64 v, float& lo, float& hi) {
    asm("mov.b64 {%0,%1},%2;" : "=f"(lo), "=f"(hi) : "l"(v));
}
__device__ __forceinline__ u64 f2fma(u64 a, u64 b, u64 c) {
    u64 d; asm("fma.rn.f32x2 %0,%1,%2,%3;" : "=l"(d) : "l"(a), "l"(b), "l"(c)); return d;
}

// ------------------------- scratch (device globals; no allocs) -------------
__device__ float2 g_ps[NBLKA * HDIM];  // BN partials (sum, sumsq)
__device__ u64    g_Meff[HDIM * 4];    // packed d-pairs: 0.5*scale[h]*M[h][:]
__device__ float  g_c2[DDIM];

// ------------------------- pass A: BN statistics of h1 ---------------------
// thread = channel; W1 column in packed regs; nc staged in smem, read LDS.128.
__global__ void __launch_bounds__(256) stats_kernel(const float* __restrict__ nf,
                                                    const int* __restrict__ ei0,
                                                    const int* __restrict__ ei1,
                                                    const float* __restrict__ W1,
                                                    const float* __restrict__ b1,
                                                    int E) {
    __shared__ ulonglong2 ncs[256 * 2];
    int t = threadIdx.x;
    u64 w0 = pk(0.5f * W1[0 * HDIM + t], 0.5f * W1[1 * HDIM + t]);
    u64 w1 = pk(0.5f * W1[2 * HDIM + t], 0.5f * W1[3 * HDIM + t]);
    u64 w2 = pk(0.5f * W1[4 * HDIM + t], 0.5f * W1[5 * HDIM + t]);
    u64 w3 = pk(0.5f * W1[6 * HDIM + t], 0.5f * W1[7 * HDIM + t]);
    u64 bp = pk(b1[t], 0.f);      // bias as chain-C: lo+hi == z + b1[t]
    float sum = 0.f, sq = 0.f;
    const float4* nfp = (const float4*)nf;

    for (int base = blockIdx.x * 256; base < E; base += gridDim.x * 256) {
        int nval = min(256, E - base);
        __syncthreads();
        if (t < nval) {
            int e = base + t;
            int s = __ldg(ei0 + e), g = __ldg(ei1 + e);
            float4 a0 = __ldg(nfp + 2 * s), a1 = __ldg(nfp + 2 * s + 1);
            float4 c0 = __ldg(nfp + 2 * g), c1 = __ldg(nfp + 2 * g + 1);
            ncs[t * 2 + 0] = make_ulonglong2(pk(a0.x + c0.x, a0.y + c0.y),
                                             pk(a0.z + c0.z, a0.w + c0.w));
            ncs[t * 2 + 1] = make_ulonglong2(pk(a1.x + c1.x, a1.y + c1.y),
                                             pk(a1.z + c1.z, a1.w + c1.w));
        }
        __syncthreads();
#pragma unroll 4
        for (int j = 0; j < nval; j++) {
            ulonglong2 p0 = ncs[j * 2 + 0];
            ulonglong2 p1 = ncs[j * 2 + 1];
            u64 s_ = f2fma(p0.x, w0, bp);
            s_ = f2fma(p0.y, w1, s_);
            s_ = f2fma(p1.x, w2, s_);
            s_ = f2fma(p1.y, w3, s_);
            float lo, hi; upk(s_, lo, hi);
            float h1 = fmaxf(lo + hi, 0.f);
            sum += h1;
            sq = fmaf(h1, h1, sq);
        }
    }
    g_ps[blockIdx.x * HDIM + t] = make_float2(sum, sq);
}

// ------------------------- setup: folds + BN finalize + c2 -----------------
// single block, 256 threads. thread t owns row h=t of every [256,8] product.
__device__ __forceinline__ void fold_rows(const float* __restrict__ A,
                                          const float* Bs, float* Os) {
    int t = threadIdx.x;
    const u64* Bp = (const u64*)Bs;
    const float* Ar = A + t * HDIM;
    u64 a0 = 0, a1 = 0, a2 = 0, a3 = 0;
#pragma unroll 8
    for (int k = 0; k < HDIM; k++) {
        float a = __ldg(Ar + k);
        u64 aa = pk(a, a);
        a0 = f2fma(aa, Bp[k * 4 + 0], a0);
        a1 = f2fma(aa, Bp[k * 4 + 1], a1);
        a2 = f2fma(aa, Bp[k * 4 + 2], a2);
        a3 = f2fma(aa, Bp[k * 4 + 3], a3);
    }
    u64* Op = (u64*)Os;
    Op[t * 4 + 0] = a0; Op[t * 4 + 1] = a1;
    Op[t * 4 + 2] = a2; Op[t * 4 + 3] = a3;
}

__global__ void __launch_bounds__(256) setup_kernel(const float* __restrict__ Wo,
                                                    const float* __restrict__ Wp,
                                                    const float* __restrict__ Wv,
                                                    const float* __restrict__ nW2,
                                                    const float* __restrict__ gamma,
                                                    const float* __restrict__ beta,
                                                    const float* __restrict__ b2,
                                                    const float* __restrict__ bv,
                                                    const float* __restrict__ bo,
                                                    const float* __restrict__ bp,
                                                    int E) {
    __shared__ float WpS[HDIM * 8], R1S[HDIM * 8], R2S[HDIM * 8], MS[HDIM * 8];
    __shared__ float sclS[HDIM], shfS[HDIM];
    int t = threadIdx.x;

    for (int i = t; i < HDIM * 8; i += 256) WpS[i] = Wp[i];
    __syncthreads();
    fold_rows(Wo, WpS, R1S);   __syncthreads();   // R1 = Wo @ Wp
    fold_rows(Wv, R1S, R2S);   __syncthreads();   // R2 = Wv @ R1
    fold_rows(nW2, R2S, MS);   __syncthreads();   // M  = nW2 @ R2

    // BN stats reduce
    float s = 0.f, q = 0.f;
#pragma unroll 8
    for (int b = 0; b < NBLKA; b++) {
        float2 p = g_ps[b * HDIM + t];
        s += p.x; q += p.y;
    }
    float invE = 1.0f / (float)E;
    float mu = s * invE;
    float var = fmaxf(q * invE - mu * mu, 0.f);
    float scl = gamma[t] * rsqrtf(var + 1e-5f);
    sclS[t] = scl;
    shfS[t] = beta[t] - mu * scl;
    __syncthreads();

    // packed Meff
#pragma unroll
    for (int p = 0; p < 4; p++)
        g_Meff[t * 4 + p] = pk(0.5f * sclS[t] * MS[t * 8 + 2 * p],
                               0.5f * sclS[t] * MS[t * 8 + 2 * p + 1]);

    // c2[d]: warp w<8 handles d=w
    int w = t >> 5, lane = t & 31;
    if (w < DDIM) {
        float r = 0.f;
#pragma unroll
        for (int i = 0; i < 8; i++) {
            int h = lane + 32 * i;
            r += shfS[h] * MS[h * 8 + w] + __ldg(b2 + h) * R2S[h * 8 + w]
               + __ldg(bv + h) * R1S[h * 8 + w] + __ldg(bo + h) * WpS[h * 8 + w];
        }
#pragma unroll
        for (int off = 16; off; off >>= 1) r += __shfl_xor_sync(0xffffffffu, r, off);
        if (lane == 0) g_c2[w] = 0.5f * (__ldg(bp + w) + r);
    }
}

// ------------------------- pass B: main (4 edges / thread) -----------------
__global__ void __launch_bounds__(256, 2) main_kernel(const float* __restrict__ edge_attr,
                                                      const float* __restrict__ nf,
                                                      const int* __restrict__ ei0,
                                                      const int* __restrict__ ei1,
                                                      const float* __restrict__ W1,
                                                      const float* __restrict__ b1,
                                                      float* __restrict__ out,
                                                      int E) {
    __shared__ ulonglong2 wp2[HDIM * 2];
    __shared__ ulonglong2 mp2[HDIM * 2];
    __shared__ u64 b1p[HDIM];
    int t = threadIdx.x;
    {
        u64* wpu = (u64*)wp2;
        u64* mpu = (u64*)mp2;
        for (int idx = t; idx < HDIM * 4; idx += 256) {
            int h = idx >> 2, p = idx & 3;
            wpu[idx] = pk(0.5f * W1[(2 * p) * HDIM + h],
                          0.5f * W1[(2 * p + 1) * HDIM + h]);
            mpu[idx] = g_Meff[idx];
        }
        b1p[t] = pk(b1[t], 0.f);
    }
    __syncthreads();

    int base = (blockIdx.x * 256 + t) * 4;
    if (base >= E) return;

    int ee[4];
#pragma unroll
    for (int i = 0; i < 4; i++) ee[i] = min(base + i, E - 1);

    const float4* nfp = (const float4*)nf;
    u64 n[4][4];
#pragma unroll
    for (int i = 0; i < 4; i++) {
        int s = __ldg(ei0 + ee[i]), g = __ldg(ei1 + ee[i]);
        float4 a0 = __ldg(nfp + 2 * s), a1 = __ldg(nfp + 2 * s + 1);
        float4 c0 = __ldg(nfp + 2 * g), c1 = __ldg(nfp + 2 * g + 1);
        n[i][0] = pk(a0.x + c0.x, a0.y + c0.y);
        n[i][1] = pk(a0.z + c0.z, a0.w + c0.w);
        n[i][2] = pk(a1.x + c1.x, a1.y + c1.y);
        n[i][3] = pk(a1.z + c1.z, a1.w + c1.w);
    }

    u64 acc[4][4];
#pragma unroll
    for (int i = 0; i < 4; i++)
#pragma unroll
        for (int p = 0; p < 4; p++) acc[i][p] = 0;

#pragma unroll 2
    for (int h = 0; h < HDIM; h++) {
        ulonglong2 wA = wp2[h * 2 + 0], wB = wp2[h * 2 + 1];
        ulonglong2 mA = mp2[h * 2 + 0], mB = mp2[h * 2 + 1];
        u64 bb = b1p[h];
#pragma unroll
        for (int i = 0; i < 4; i++) {
            u64 s_ = f2fma(n[i][0], wA.x, bb);
            s_ = f2fma(n[i][1], wA.y, s_);
            s_ = f2fma(n[i][2], wB.x, s_);
            s_ = f2fma(n[i][3], wB.y, s_);
            float lo, hi; upk(s_, lo, hi);
            float h1 = fmaxf(lo + hi, 0.f);
            u64 hh = pk(h1, h1);
            acc[i][0] = f2fma(hh, mA.x, acc[i][0]);
            acc[i][1] = f2fma(hh, mA.y, acc[i][1]);
            acc[i][2] = f2fma(hh, mB.x, acc[i][2]);
            acc[i][3] = f2fma(hh, mB.y, acc[i][3]);
        }
    }

    float cz[8];
#pragma unroll
    for (int d = 0; d < 8; d++) cz[d] = g_c2[d];

    const float4* eap = (const float4*)edge_attr;
    float4* outp = (float4*)out;
#pragma unroll
    for (int i = 0; i < 4; i++) {
        int e = base + i;
        if (e >= E) break;
        float4 e0 = __ldg(eap + e * 2), e1 = __ldg(eap + e * 2 + 1);
        float x0, x1, x2, x3, x4, x5, x6, x7;
        upk(acc[i][0], x0, x1); upk(acc[i][1], x2, x3);
        upk(acc[i][2], x4, x5); upk(acc[i][3], x6, x7);
        float4 o0, o1;
        o0.x = e0.x + x0 + cz[0]; o0.y = e0.y + x1 + cz[1];
        o0.z = e0.z + x2 + cz[2]; o0.w = e0.w + x3 + cz[3];
        o1.x = e1.x + x4 + cz[4]; o1.y = e1.y + x5 + cz[5];
        o1.z = e1.z + x6 + cz[6]; o1.w = e1.w + x7 + cz[7];
        outp[e * 2] = o0; outp[e * 2 + 1] = o1;
    }
}

// ------------------------- launch ------------------------------------------
extern "C" void kernel_launch(void* const* d_in, const int* in_sizes, int n_in,
                              void* d_out, int out_size) {
    const float* edge_attr = (const float*)d_in[0];
    const float* nf        = (const float*)d_in[1];
    const int*   ei        = (const int*)  d_in[2];
    // d_in[3..8] = edge encoder params: dead code in the reference, unused.
    const float* nW1   = (const float*)d_in[9];
    const float* nb1   = (const float*)d_in[10];
    const float* ngam  = (const float*)d_in[11];
    const float* nbet  = (const float*)d_in[12];
    const float* nW2   = (const float*)d_in[13];
    const float* nb2   = (const float*)d_in[14];
    const float* Wv    = (const float*)d_in[15];
    const float* bv    = (const float*)d_in[16];
    const float* Wo    = (const float*)d_in[17];
    const float* bo    = (const float*)d_in[18];
    const float* Wp    = (const float*)d_in[19];
    const float* bp    = (const float*)d_in[20];
    (void)n_in; (void)out_size;

    int E = in_sizes[0] / DDIM;
    const int* ei0 = ei;
    const int* ei1 = ei + E;
    float* out = (float*)d_out;

    // BN statistics (longest chain starts immediately)
    stats_kernel<<<NBLKA, 256>>>(nf, ei0, ei1, nW1, nb1, E);

    // folds + BN finalize + c2, one single-block kernel
    setup_kernel<<<1, 256>>>(Wo, Wp, Wv, nW2, ngam, nbet, nb2, bv, bo, bp, E);

    // main fused pass, 4 edges / thread
    int gridB = (E + 1023) / 1024;
    main_kernel<<<gridB, 256>>>(edge_attr, nf, ei0, ei1, nW1, nb1, out, E);
}

// round 7
// speedup vs baseline: 1.1252x; 1.1252x over previous
#include <cuda_runtime.h>
#include <math.h>

// ---------------------------------------------------------------------------
// CausalEdgeAttention — algebraically reduced:
//   out = edge_attr + relu(nc@W1eff + b1) @ Meff + c2
//   nc    = nf[src]+nf[tgt]          (0.5 folded into W1eff = 0.5*n_W1)
//   Meff  = 0.5 * diag(scale) * M,   M = n_W2 @ Wv @ Wo @ Wp
//   c2    = 0.5 * (b2@R2 + bv@R1 + bo@Wp + bp + shift@M)
//   scale = gamma*rsqrt(var+eps), shift = beta - mu*scale (BN stats of h1)
// Edge encoder in the reference is dead code -> skipped.
// stats: tf32 tensor-core (bias via C operand, in-lane column accumulation).
// main:  scalar f32x2 (R4 proven config).
// ---------------------------------------------------------------------------

#define HDIM 256
#define DDIM 8
#define SGRID 512

typedef unsigned long long u64;
typedef unsigned int u32;

__device__ __forceinline__ u64 pk(float lo, float hi) {
    u64 r; asm("mov.b64 %0,{%1,%2};" : "=l"(r) : "f"(lo), "f"(hi)); return r;
}
__device__ __forceinline__ void upk(u64 v, float& lo, float& hi) {
    asm("mov.b64 {%0,%1},%2;" : "=f"(lo), "=f"(hi) : "l"(v));
}
__device__ __forceinline__ u64 f2fma(u64 a, u64 b, u64 c) {
    u64 d; asm("fma.rn.f32x2 %0,%1,%2,%3;" : "=l"(d) : "l"(a), "l"(b), "l"(c)); return d;
}
__device__ __forceinline__ u32 cvt_tf32(float f) {
    u32 r; asm("cvt.rna.tf32.f32 %0, %1;" : "=r"(r) : "f"(f)); return r;
}

// ------------------------- scratch (device globals; no allocs) -------------
__device__ float2 g_ps[SGRID * HDIM];  // BN partials (sum, sumsq) per block/ch
__device__ u64    g_Meff[HDIM * 4];    // packed d-pairs: 0.5*scale[h]*M[h][:]
__device__ float  g_c2[DDIM];

// ------------------------- pass A: BN statistics via tf32 MMA --------------
// Block: 8 warps; stages 128 edges/round into A-fragment planes.
// Warp w owns channel-chunks j=4w..4w+3 (B-frags + biases in registers).
__global__ void __launch_bounds__(256) stats_kernel(const float* __restrict__ nf,
                                                    const int* __restrict__ ei0,
                                                    const int* __restrict__ ei1,
                                                    const float* __restrict__ W1,
                                                    const float* __restrict__ b1,
                                                    int fullE) {
    __shared__ float aS[4][8][32];   // [A-frag slot][subtile][lane]
    int t = threadIdx.x, w = t >> 5, l = t & 31;
    int g = l >> 2, c = l & 3;

    u32 Bf0[4], Bf1[4];
    float cbl[4], cbh[4];
#pragma unroll
    for (int jj = 0; jj < 4; jj++) {
        int j = 4 * w + jj, n = 8 * j + g;
        Bf0[jj] = cvt_tf32(0.5f * __ldg(W1 + c * HDIM + n));
        Bf1[jj] = cvt_tf32(0.5f * __ldg(W1 + (c + 4) * HDIM + n));
        cbl[jj] = __ldg(b1 + 8 * j + 2 * c);
        cbh[jj] = __ldg(b1 + 8 * j + 2 * c + 1);
    }
    float sL[4] = {0.f, 0.f, 0.f, 0.f}, sH[4] = {0.f, 0.f, 0.f, 0.f};
    float qL[4] = {0.f, 0.f, 0.f, 0.f}, qH[4] = {0.f, 0.f, 0.f, 0.f};
    const float4* nfp = (const float4*)nf;

    for (int base = blockIdx.x * 128; base < fullE; base += SGRID * 128) {
        __syncthreads();
        if (t < 128) {
            int e = base + t;
            if (e < fullE) {
                int r = t & 15, tt = t >> 4;
                int si = __ldg(ei0 + e), ti = __ldg(ei1 + e);
                float4 s0 = __ldg(nfp + 2 * si), s1 = __ldg(nfp + 2 * si + 1);
                float4 u0 = __ldg(nfp + 2 * ti), u1 = __ldg(nfp + 2 * ti + 1);
                float v[8];
                v[0] = s0.x + u0.x; v[1] = s0.y + u0.y;
                v[2] = s0.z + u0.z; v[3] = s0.w + u0.w;
                v[4] = s1.x + u1.x; v[5] = s1.y + u1.y;
                v[6] = s1.z + u1.z; v[7] = s1.w + u1.w;
                int rr = r & 7, hi = r >> 3;
#pragma unroll
                for (int cc = 0; cc < 4; cc++) {
                    aS[hi][tt][rr * 4 + cc]     = __uint_as_float(cvt_tf32(v[cc]));
                    aS[2 + hi][tt][rr * 4 + cc] = __uint_as_float(cvt_tf32(v[cc + 4]));
                }
            }
        }
        __syncthreads();
#pragma unroll
        for (int tt = 0; tt < 8; tt++) {
            if (base + 16 * tt >= fullE) break;
            u32 A0 = __float_as_uint(aS[0][tt][l]);
            u32 A1 = __float_as_uint(aS[1][tt][l]);
            u32 A2 = __float_as_uint(aS[2][tt][l]);
            u32 A3 = __float_as_uint(aS[3][tt][l]);
#pragma unroll
            for (int jj = 0; jj < 4; jj++) {
                float d0, d1, d2, d3;
                asm volatile(
                    "mma.sync.aligned.m16n8k8.row.col.f32.tf32.tf32.f32 "
                    "{%0,%1,%2,%3}, {%4,%5,%6,%7}, {%8,%9}, {%10,%11,%12,%13};\n"
                    : "=f"(d0), "=f"(d1), "=f"(d2), "=f"(d3)
                    : "r"(A0), "r"(A1), "r"(A2), "r"(A3),
                      "r"(Bf0[jj]), "r"(Bf1[jj]),
                      "f"(cbl[jj]), "f"(cbh[jj]), "f"(cbl[jj]), "f"(cbh[jj]));
                float r0 = fmaxf(d0, 0.f), r1 = fmaxf(d1, 0.f);
                float r2 = fmaxf(d2, 0.f), r3 = fmaxf(d3, 0.f);
                sL[jj] += r0 + r2;
                sH[jj] += r1 + r3;
                qL[jj] = fmaf(r0, r0, qL[jj]); qL[jj] = fmaf(r2, r2, qL[jj]);
                qH[jj] = fmaf(r1, r1, qH[jj]); qH[jj] = fmaf(r3, r3, qH[jj]);
            }
        }
    }
    // reduce over edge-row groups g (lane bits 2..4)
#pragma unroll
    for (int jj = 0; jj < 4; jj++)
#pragma unroll
        for (int off = 4; off <= 16; off <<= 1) {
            sL[jj] += __shfl_xor_sync(0xffffffffu, sL[jj], off);
            sH[jj] += __shfl_xor_sync(0xffffffffu, sH[jj], off);
            qL[jj] += __shfl_xor_sync(0xffffffffu, qL[jj], off);
            qH[jj] += __shfl_xor_sync(0xffffffffu, qH[jj], off);
        }
    if (g == 0) {
#pragma unroll
        for (int jj = 0; jj < 4; jj++) {
            int ch = 8 * (4 * w + jj) + 2 * c;
            g_ps[blockIdx.x * HDIM + ch]     = make_float2(sL[jj], qL[jj]);
            g_ps[blockIdx.x * HDIM + ch + 1] = make_float2(sH[jj], qH[jj]);
        }
    }
}

// ------------------------- setup: folds + BN finalize + c2 -----------------
__device__ __forceinline__ void fold_rows(const float* __restrict__ A,
                                          const float* Bs, float* Os) {
    int t = threadIdx.x;
    const u64* Bp = (const u64*)Bs;
    const float* Ar = A + t * HDIM;
    u64 a0 = 0, a1 = 0, a2 = 0, a3 = 0;
#pragma unroll 8
    for (int k = 0; k < HDIM; k++) {
        float a = __ldg(Ar + k);
        u64 aa = pk(a, a);
        a0 = f2fma(aa, Bp[k * 4 + 0], a0);
        a1 = f2fma(aa, Bp[k * 4 + 1], a1);
        a2 = f2fma(aa, Bp[k * 4 + 2], a2);
        a3 = f2fma(aa, Bp[k * 4 + 3], a3);
    }
    u64* Op = (u64*)Os;
    Op[t * 4 + 0] = a0; Op[t * 4 + 1] = a1;
    Op[t * 4 + 2] = a2; Op[t * 4 + 3] = a3;
}

__global__ void __launch_bounds__(256) setup_kernel(const float* __restrict__ Wo,
                                                    const float* __restrict__ Wp,
                                                    const float* __restrict__ Wv,
                                                    const float* __restrict__ nW2,
                                                    const float* __restrict__ gamma,
                                                    const float* __restrict__ beta,
                                                    const float* __restrict__ b2,
                                                    const float* __restrict__ bv,
                                                    const float* __restrict__ bo,
                                                    const float* __restrict__ bp,
                                                    const float* __restrict__ nf,
                                                    const int* __restrict__ ei0,
                                                    const int* __restrict__ ei1,
                                                    const float* __restrict__ W1,
                                                    const float* __restrict__ b1,
                                                    int fullE, int E) {
    __shared__ float WpS[HDIM * 8], R1S[HDIM * 8], R2S[HDIM * 8], MS[HDIM * 8];
    __shared__ float sclS[HDIM], shfS[HDIM];
    int t = threadIdx.x;

    for (int i = t; i < HDIM * 8; i += 256) WpS[i] = Wp[i];
    __syncthreads();
    fold_rows(Wo, WpS, R1S);   __syncthreads();   // R1 = Wo @ Wp
    fold_rows(Wv, R1S, R2S);   __syncthreads();   // R2 = Wv @ R1
    fold_rows(nW2, R2S, MS);   __syncthreads();   // M  = nW2 @ R2

    // BN stats reduce
    float s = 0.f, q = 0.f;
#pragma unroll 8
    for (int b = 0; b < SGRID; b++) {
        float2 p = g_ps[b * HDIM + t];
        s += p.x; q += p.y;
    }
    // tail edges (E % 16), scalar exact
    for (int e = fullE; e < E; e++) {
        int si = __ldg(ei0 + e), ti = __ldg(ei1 + e);
        float z = __ldg(b1 + t);
#pragma unroll
        for (int k = 0; k < 8; k++)
            z = fmaf(0.5f * (__ldg(nf + si * 8 + k) + __ldg(nf + ti * 8 + k)),
                     __ldg(W1 + k * HDIM + t), z);
        float h = fmaxf(z, 0.f);
        s += h; q = fmaf(h, h, q);
    }

    float invE = 1.0f / (float)E;
    float mu = s * invE;
    float var = fmaxf(q * invE - mu * mu, 0.f);
    float scl = gamma[t] * rsqrtf(var + 1e-5f);
    sclS[t] = scl;
    shfS[t] = beta[t] - mu * scl;
    __syncthreads();

    // packed Meff
#pragma unroll
    for (int p = 0; p < 4; p++)
        g_Meff[t * 4 + p] = pk(0.5f * sclS[t] * MS[t * 8 + 2 * p],
                               0.5f * sclS[t] * MS[t * 8 + 2 * p + 1]);

    // c2[d]: warp w<8 handles d=w
    int w = t >> 5, lane = t & 31;
    if (w < DDIM) {
        float r = 0.f;
#pragma unroll
        for (int i = 0; i < 8; i++) {
            int h = lane + 32 * i;
            r += shfS[h] * MS[h * 8 + w] + __ldg(b2 + h) * R2S[h * 8 + w]
               + __ldg(bv + h) * R1S[h * 8 + w] + __ldg(bo + h) * WpS[h * 8 + w];
        }
#pragma unroll
        for (int off = 16; off; off >>= 1) r += __shfl_xor_sync(0xffffffffu, r, off);
        if (lane == 0) g_c2[w] = 0.5f * (__ldg(bp + w) + r);
    }
}

// ------------------------- pass B: main (4 edges / thread, R4 config) ------
__global__ void __launch_bounds__(256, 2) main_kernel(const float* __restrict__ edge_attr,
                                                      const float* __restrict__ nf,
                                                      const int* __restrict__ ei0,
                                                      const int* __restrict__ ei1,
                                                      const float* __restrict__ W1,
                                                      const float* __restrict__ b1,
                                                      float* __restrict__ out,
                                                      int E) {
    __shared__ u64 wp[HDIM * 4];
    __shared__ u64 mp[HDIM * 4];
    __shared__ float b1s[HDIM];
    int t = threadIdx.x;
    for (int idx = t; idx < HDIM * 4; idx += 256) {
        int h = idx >> 2, p = idx & 3;
        wp[idx] = pk(0.5f * W1[(2 * p) * HDIM + h], 0.5f * W1[(2 * p + 1) * HDIM + h]);
        mp[idx] = g_Meff[idx];
    }
    b1s[t] = b1[t];
    __syncthreads();

    int base = (blockIdx.x * 256 + t) * 4;
    if (base >= E) return;

    int ee[4];
#pragma unroll
    for (int i = 0; i < 4; i++) ee[i] = min(base + i, E - 1);

    const float4* nfp = (const float4*)nf;
    u64 n[4][4];
#pragma unroll
    for (int i = 0; i < 4; i++) {
        int s = __ldg(ei0 + ee[i]), g = __ldg(ei1 + ee[i]);
        float4 a0 = __ldg(nfp + 2 * s), a1 = __ldg(nfp + 2 * s + 1);
        float4 c0 = __ldg(nfp + 2 * g), c1 = __ldg(nfp + 2 * g + 1);
        n[i][0] = pk(a0.x + c0.x, a0.y + c0.y);
        n[i][1] = pk(a0.z + c0.z, a0.w + c0.w);
        n[i][2] = pk(a1.x + c1.x, a1.y + c1.y);
        n[i][3] = pk(a1.z + c1.z, a1.w + c1.w);
    }

    u64 acc[4][4];
#pragma unroll
    for (int i = 0; i < 4; i++)
#pragma unroll
        for (int p = 0; p < 4; p++) acc[i][p] = 0;

#pragma unroll 2
    for (int h = 0; h < HDIM; h++) {
        u64 w0 = wp[h * 4 + 0], w1 = wp[h * 4 + 1], w2 = wp[h * 4 + 2], w3 = wp[h * 4 + 3];
        u64 m0 = mp[h * 4 + 0], m1 = mp[h * 4 + 1], m2 = mp[h * 4 + 2], m3 = mp[h * 4 + 3];
        float bb = b1s[h];
#pragma unroll
        for (int i = 0; i < 4; i++) {
            u64 s_ = f2fma(n[i][0], w0, pk(bb, 0.f));
            s_ = f2fma(n[i][1], w1, s_);
            s_ = f2fma(n[i][2], w2, s_);
            s_ = f2fma(n[i][3], w3, s_);
            float lo, hi; upk(s_, lo, hi);
            float h1 = fmaxf(lo + hi, 0.f);
            u64 hh = pk(h1, h1);
            acc[i][0] = f2fma(hh, m0, acc[i][0]);
            acc[i][1] = f2fma(hh, m1, acc[i][1]);
            acc[i][2] = f2fma(hh, m2, acc[i][2]);
            acc[i][3] = f2fma(hh, m3, acc[i][3]);
        }
    }

    float cz[8];
#pragma unroll
    for (int d = 0; d < 8; d++) cz[d] = g_c2[d];

    const float4* eap = (const float4*)edge_attr;
    float4* outp = (float4*)out;
#pragma unroll
    for (int i = 0; i < 4; i++) {
        int e = base + i;
        if (e >= E) break;
        float4 e0 = __ldg(eap + e * 2), e1 = __ldg(eap + e * 2 + 1);
        float x0, x1, x2, x3, x4, x5, x6, x7;
        upk(acc[i][0], x0, x1); upk(acc[i][1], x2, x3);
        upk(acc[i][2], x4, x5); upk(acc[i][3], x6, x7);
        float4 o0, o1;
        o0.x = e0.x + x0 + cz[0]; o0.y = e0.y + x1 + cz[1];
        o0.z = e0.z + x2 + cz[2]; o0.w = e0.w + x3 + cz[3];
        o1.x = e1.x + x4 + cz[4]; o1.y = e1.y + x5 + cz[5];
        o1.z = e1.z + x6 + cz[6]; o1.w = e1.w + x7 + cz[7];
        outp[e * 2] = o0; outp[e * 2 + 1] = o1;
    }
}

// ------------------------- launch ------------------------------------------
extern "C" void kernel_launch(void* const* d_in, const int* in_sizes, int n_in,
                              void* d_out, int out_size) {
    const float* edge_attr = (const float*)d_in[0];
    const float* nf        = (const float*)d_in[1];
    const int*   ei        = (const int*)  d_in[2];
    // d_in[3..8] = edge encoder params: dead code in the reference, unused.
    const float* nW1   = (const float*)d_in[9];
    const float* nb1   = (const float*)d_in[10];
    const float* ngam  = (const float*)d_in[11];
    const float* nbet  = (const float*)d_in[12];
    const float* nW2   = (const float*)d_in[13];
    const float* nb2   = (const float*)d_in[14];
    const float* Wv    = (const float*)d_in[15];
    const float* bv    = (const float*)d_in[16];
    const float* Wo    = (const float*)d_in[17];
    const float* bo    = (const float*)d_in[18];
    const float* Wp    = (const float*)d_in[19];
    const float* bp    = (const float*)d_in[20];
    (void)n_in; (void)out_size;

    int E = in_sizes[0] / DDIM;
    const int* ei0 = ei;
    const int* ei1 = ei + E;
    float* out = (float*)d_out;
    int fullE = (E / 16) * 16;

    // BN statistics via tensor cores (longest chain starts immediately)
    stats_kernel<<<SGRID, 256>>>(nf, ei0, ei1, nW1, nb1, fullE);

    // folds + BN finalize (incl. tail edges) + c2, one single-block kernel
    setup_kernel<<<1, 256>>>(Wo, Wp, Wv, nW2, ngam, nbet, nb2, bv, bo, bp,
                             nf, ei0, ei1, nW1, nb1, fullE, E);

    // main fused pass, 4 edges / thread (R4 proven config)
    int gridB = (E + 1023) / 1024;
    main_kernel<<<gridB, 256>>>(edge_attr, nf, ei0, ei1, nW1, nb1, out, E);
}

// round 8
// speedup vs baseline: 1.9488x; 1.7320x over previous
#include <cuda_runtime.h>
#include <math.h>

// ---------------------------------------------------------------------------
// CausalEdgeAttention — algebraically reduced:
//   out = edge_attr + relu(nc@W1eff + b1) @ Meff + c2
//   nc    = nf[src]+nf[tgt]          (0.5 folded into W1eff = 0.5*n_W1)
//   Meff  = 0.5 * diag(scale) * M,   M = n_W2 @ Wv @ Wo @ Wp
//   c2    = 0.5 * (b2@R2 + bv@R1 + bo@Wp + bp + shift@M)
//   scale = gamma*rsqrt(var+eps), shift = beta - mu*scale (BN stats of h1)
// Edge encoder in the reference is dead code -> skipped.
// stats: tf32 tensor-core (proven 37us). folds: grid-32 (proven 6.9us each).
// reduce: grid-256 (block-per-channel). main: exact R4 scalar f32x2 (proven).
// ---------------------------------------------------------------------------

#define HDIM 256
#define DDIM 8
#define SGRID 512

typedef unsigned long long u64;
typedef unsigned int u32;

__device__ __forceinline__ u64 pk(float lo, float hi) {
    u64 r; asm("mov.b64 %0,{%1,%2};" : "=l"(r) : "f"(lo), "f"(hi)); return r;
}
__device__ __forceinline__ void upk(u64 v, float& lo, float& hi) {
    asm("mov.b64 {%0,%1},%2;" : "=f"(lo), "=f"(hi) : "l"(v));
}
__device__ __forceinline__ u64 f2mul(u64 a, u64 b) {
    u64 d; asm("mul.rn.f32x2 %0,%1,%2;" : "=l"(d) : "l"(a), "l"(b)); return d;
}
__device__ __forceinline__ u64 f2fma(u64 a, u64 b, u64 c) {
    u64 d; asm("fma.rn.f32x2 %0,%1,%2,%3;" : "=l"(d) : "l"(a), "l"(b), "l"(c)); return d;
}
__device__ __forceinline__ u32 cvt_tf32(float f) {
    u32 r; asm("cvt.rna.tf32.f32 %0, %1;" : "=r"(r) : "f"(f)); return r;
}

// ------------------------- scratch (device globals; no allocs) -------------
__device__ float  g_R1[HDIM * DDIM];   // Wo @ Wp
__device__ float  g_R2[HDIM * DDIM];   // Wv @ R1
__device__ float  g_M [HDIM * DDIM];   // n_W2 @ R2
__device__ float2 g_ps[SGRID * HDIM];  // BN partials (sum, sumsq)
__device__ float  g_scl[HDIM];         // BN scale per channel
__device__ float  g_shf[HDIM];         // BN shift per channel
__device__ u64    g_Meff[HDIM * 4];    // packed d-pairs: 0.5*scale[h]*M[h][:]
__device__ float  g_c2[DDIM];

// ------------------------- pass A: BN statistics via tf32 MMA --------------
__global__ void __launch_bounds__(256) stats_kernel(const float* __restrict__ nf,
                                                    const int* __restrict__ ei0,
                                                    const int* __restrict__ ei1,
                                                    const float* __restrict__ W1,
                                                    const float* __restrict__ b1,
                                                    int fullE) {
    __shared__ float aS[4][8][32];   // [A-frag slot][subtile][lane]
    int t = threadIdx.x, w = t >> 5, l = t & 31;
    int g = l >> 2, c = l & 3;

    u32 Bf0[4], Bf1[4];
    float cbl[4], cbh[4];
#pragma unroll
    for (int jj = 0; jj < 4; jj++) {
        int j = 4 * w + jj, n = 8 * j + g;
        Bf0[jj] = cvt_tf32(0.5f * __ldg(W1 + c * HDIM + n));
        Bf1[jj] = cvt_tf32(0.5f * __ldg(W1 + (c + 4) * HDIM + n));
        cbl[jj] = __ldg(b1 + 8 * j + 2 * c);
        cbh[jj] = __ldg(b1 + 8 * j + 2 * c + 1);
    }
    float sL[4] = {0.f, 0.f, 0.f, 0.f}, sH[4] = {0.f, 0.f, 0.f, 0.f};
    float qL[4] = {0.f, 0.f, 0.f, 0.f}, qH[4] = {0.f, 0.f, 0.f, 0.f};
    const float4* nfp = (const float4*)nf;

    for (int base = blockIdx.x * 128; base < fullE; base += SGRID * 128) {
        __syncthreads();
        if (t < 128) {
            int e = base + t;
            if (e < fullE) {
                int r = t & 15, tt = t >> 4;
                int si = __ldg(ei0 + e), ti = __ldg(ei1 + e);
                float4 s0 = __ldg(nfp + 2 * si), s1 = __ldg(nfp + 2 * si + 1);
                float4 u0 = __ldg(nfp + 2 * ti), u1 = __ldg(nfp + 2 * ti + 1);
                float v[8];
                v[0] = s0.x + u0.x; v[1] = s0.y + u0.y;
                v[2] = s0.z + u0.z; v[3] = s0.w + u0.w;
                v[4] = s1.x + u1.x; v[5] = s1.y + u1.y;
                v[6] = s1.z + u1.z; v[7] = s1.w + u1.w;
                int rr = r & 7, hi = r >> 3;
#pragma unroll
                for (int cc = 0; cc < 4; cc++) {
                    aS[hi][tt][rr * 4 + cc]     = __uint_as_float(cvt_tf32(v[cc]));
                    aS[2 + hi][tt][rr * 4 + cc] = __uint_as_float(cvt_tf32(v[cc + 4]));
                }
            }
        }
        __syncthreads();
#pragma unroll
        for (int tt = 0; tt < 8; tt++) {
            if (base + 16 * tt >= fullE) break;
            u32 A0 = __float_as_uint(aS[0][tt][l]);
            u32 A1 = __float_as_uint(aS[1][tt][l]);
            u32 A2 = __float_as_uint(aS[2][tt][l]);
            u32 A3 = __float_as_uint(aS[3][tt][l]);
#pragma unroll
            for (int jj = 0; jj < 4; jj++) {
                float d0, d1, d2, d3;
                asm volatile(
                    "mma.sync.aligned.m16n8k8.row.col.f32.tf32.tf32.f32 "
                    "{%0,%1,%2,%3}, {%4,%5,%6,%7}, {%8,%9}, {%10,%11,%12,%13};\n"
                    : "=f"(d0), "=f"(d1), "=f"(d2), "=f"(d3)
                    : "r"(A0), "r"(A1), "r"(A2), "r"(A3),
                      "r"(Bf0[jj]), "r"(Bf1[jj]),
                      "f"(cbl[jj]), "f"(cbh[jj]), "f"(cbl[jj]), "f"(cbh[jj]));
                float r0 = fmaxf(d0, 0.f), r1 = fmaxf(d1, 0.f);
                float r2 = fmaxf(d2, 0.f), r3 = fmaxf(d3, 0.f);
                sL[jj] += r0 + r2;
                sH[jj] += r1 + r3;
                qL[jj] = fmaf(r0, r0, qL[jj]); qL[jj] = fmaf(r2, r2, qL[jj]);
                qH[jj] = fmaf(r1, r1, qH[jj]); qH[jj] = fmaf(r3, r3, qH[jj]);
            }
        }
    }
#pragma unroll
    for (int jj = 0; jj < 4; jj++)
#pragma unroll
        for (int off = 4; off <= 16; off <<= 1) {
            sL[jj] += __shfl_xor_sync(0xffffffffu, sL[jj], off);
            sH[jj] += __shfl_xor_sync(0xffffffffu, sH[jj], off);
            qL[jj] += __shfl_xor_sync(0xffffffffu, qL[jj], off);
            qH[jj] += __shfl_xor_sync(0xffffffffu, qH[jj], off);
        }
    if (g == 0) {
#pragma unroll
        for (int jj = 0; jj < 4; jj++) {
            int ch = 8 * (4 * w + jj) + 2 * c;
            g_ps[blockIdx.x * HDIM + ch]     = make_float2(sL[jj], qL[jj]);
            g_ps[blockIdx.x * HDIM + ch + 1] = make_float2(sH[jj], qH[jj]);
        }
    }
}

// ------------------------- fold: Out[H,8] = A[H,H] @ B[H,8] (R4 proven) ----
__global__ void __launch_bounds__(256) fold_kernel(const float* __restrict__ A,
                                                   const float* __restrict__ Bext,
                                                   int mode) {
    __shared__ u64 Bs[HDIM * 4];
    const u64* Bv = (mode == 0) ? (const u64*)Bext
                   : (mode == 1) ? (const u64*)g_R1 : (const u64*)g_R2;
    float* Out = (mode == 0) ? g_R1 : (mode == 1) ? g_R2 : g_M;
    int t = threadIdx.x;
    for (int i = t; i < HDIM * 4; i += 256) Bs[i] = Bv[i];
    __syncthreads();

    int h = blockIdx.x * 8 + (t >> 5);
    int lane = t & 31;
    const float* Ar = A + h * HDIM;
    u64 a0 = 0, a1 = 0, a2 = 0, a3 = 0;
#pragma unroll
    for (int i = 0; i < 8; i++) {
        int k = lane + 32 * i;
        float a = __ldg(Ar + k);
        u64 aa = pk(a, a);
        a0 = f2fma(aa, Bs[k * 4 + 0], a0);
        a1 = f2fma(aa, Bs[k * 4 + 1], a1);
        a2 = f2fma(aa, Bs[k * 4 + 2], a2);
        a3 = f2fma(aa, Bs[k * 4 + 3], a3);
    }
    float r[8];
    upk(a0, r[0], r[1]); upk(a1, r[2], r[3]);
    upk(a2, r[4], r[5]); upk(a3, r[6], r[7]);
#pragma unroll
    for (int off = 16; off; off >>= 1)
#pragma unroll
        for (int d = 0; d < 8; d++) r[d] += __shfl_xor_sync(0xffffffffu, r[d], off);
    if (lane == 0) {
        float4* o = (float4*)(Out + h * 8);
        o[0] = make_float4(r[0], r[1], r[2], r[3]);
        o[1] = make_float4(r[4], r[5], r[6], r[7]);
    }
}

// ------------------------- BN reduce: one block per channel ----------------
__global__ void __launch_bounds__(256) reduce_kernel(const float* __restrict__ gamma,
                                                     const float* __restrict__ beta,
                                                     const float* __restrict__ nf,
                                                     const int* __restrict__ ei0,
                                                     const int* __restrict__ ei1,
                                                     const float* __restrict__ W1,
                                                     const float* __restrict__ b1,
                                                     int fullE, int E) {
    __shared__ float ss[8], qq[8];
    int h = blockIdx.x, t = threadIdx.x;
    float2 p0 = g_ps[t * HDIM + h];
    float2 p1 = g_ps[(t + 256) * HDIM + h];
    float s = p0.x + p1.x, q = p0.y + p1.y;
#pragma unroll
    for (int off = 16; off; off >>= 1) {
        s += __shfl_xor_sync(0xffffffffu, s, off);
        q += __shfl_xor_sync(0xffffffffu, q, off);
    }
    if ((t & 31) == 0) { ss[t >> 5] = s; qq[t >> 5] = q; }
    __syncthreads();
    if (t == 0) {
        s = 0.f; q = 0.f;
#pragma unroll
        for (int i = 0; i < 8; i++) { s += ss[i]; q += qq[i]; }
        // scalar tail (E % 16 edges), exact
        for (int e = fullE; e < E; e++) {
            int si = __ldg(ei0 + e), ti = __ldg(ei1 + e);
            float z = __ldg(b1 + h);
#pragma unroll
            for (int k = 0; k < 8; k++)
                z = fmaf(0.5f * (__ldg(nf + si * 8 + k) + __ldg(nf + ti * 8 + k)),
                         __ldg(W1 + k * HDIM + h), z);
            float hv = fmaxf(z, 0.f);
            s += hv; q = fmaf(hv, hv, q);
        }
        float invE = 1.0f / (float)E;
        float mu = s * invE;
        float var = fmaxf(q * invE - mu * mu, 0.f);
        float scl = gamma[h] * rsqrtf(var + 1e-5f);
        g_scl[h] = scl;
        g_shf[h] = beta[h] - mu * scl;
    }
}

// ------------------------- final: pack Meff + compute c2 -------------------
__global__ void __launch_bounds__(256) final_kernel(const float* __restrict__ b2,
                                                    const float* __restrict__ bv,
                                                    const float* __restrict__ bo,
                                                    const float* __restrict__ bp,
                                                    const float* __restrict__ Wp) {
    int t = threadIdx.x;
    float scl = g_scl[t];
#pragma unroll
    for (int p = 0; p < 4; p++)
        g_Meff[t * 4 + p] = pk(0.5f * scl * g_M[t * 8 + 2 * p],
                               0.5f * scl * g_M[t * 8 + 2 * p + 1]);

    int w = t >> 5, lane = t & 31;
    if (w < DDIM) {
        float r = 0.f;
#pragma unroll
        for (int i = 0; i < 8; i++) {
            int h = lane + 32 * i;
            r += g_shf[h] * g_M[h * 8 + w] + __ldg(b2 + h) * g_R2[h * 8 + w]
               + __ldg(bv + h) * g_R1[h * 8 + w] + __ldg(bo + h) * __ldg(Wp + h * 8 + w);
        }
#pragma unroll
        for (int off = 16; off; off >>= 1) r += __shfl_xor_sync(0xffffffffu, r, off);
        if (lane == 0) g_c2[w] = 0.5f * (__ldg(bp + w) + r);
    }
}

// ------------------------- pass B: main (exact R4 proven config) -----------
__global__ void __launch_bounds__(256, 2) main_kernel(const float* __restrict__ edge_attr,
                                                      const float* __restrict__ nf,
                                                      const int* __restrict__ ei0,
                                                      const int* __restrict__ ei1,
                                                      const float* __restrict__ W1,
                                                      const float* __restrict__ b1,
                                                      float* __restrict__ out,
                                                      int E) {
    __shared__ u64 wp[HDIM * 4];
    __shared__ u64 mp[HDIM * 4];
    __shared__ float b1s[HDIM];
    int t = threadIdx.x;
    for (int idx = t; idx < HDIM * 4; idx += 256) {
        int h = idx >> 2, p = idx & 3;
        wp[idx] = pk(0.5f * W1[(2 * p) * HDIM + h], 0.5f * W1[(2 * p + 1) * HDIM + h]);
        mp[idx] = g_Meff[idx];
    }
    b1s[t] = b1[t];
    __syncthreads();

    int base = (blockIdx.x * 256 + t) * 4;
    if (base >= E) return;

    int ee[4];
#pragma unroll
    for (int i = 0; i < 4; i++) ee[i] = min(base + i, E - 1);

    const float4* nfp = (const float4*)nf;
    u64 n[4][4];
#pragma unroll
    for (int i = 0; i < 4; i++) {
        int s = __ldg(ei0 + ee[i]), g = __ldg(ei1 + ee[i]);
        float4 a0 = __ldg(nfp + 2 * s), a1 = __ldg(nfp + 2 * s + 1);
        float4 c0 = __ldg(nfp + 2 * g), c1 = __ldg(nfp + 2 * g + 1);
        n[i][0] = pk(a0.x + c0.x, a0.y + c0.y);
        n[i][1] = pk(a0.z + c0.z, a0.w + c0.w);
        n[i][2] = pk(a1.x + c1.x, a1.y + c1.y);
        n[i][3] = pk(a1.z + c1.z, a1.w + c1.w);
    }

    u64 acc[4][4];
#pragma unroll
    for (int i = 0; i < 4; i++)
#pragma unroll
        for (int p = 0; p < 4; p++) acc[i][p] = 0;

#pragma unroll 2
    for (int h = 0; h < HDIM; h++) {
        u64 w0 = wp[h * 4 + 0], w1 = wp[h * 4 + 1], w2 = wp[h * 4 + 2], w3 = wp[h * 4 + 3];
        u64 m0 = mp[h * 4 + 0], m1 = mp[h * 4 + 1], m2 = mp[h * 4 + 2], m3 = mp[h * 4 + 3];
        float bb = b1s[h];
#pragma unroll
        for (int i = 0; i < 4; i++) {
            u64 s_ = f2mul(n[i][0], w0);
            s_ = f2fma(n[i][1], w1, s_);
            s_ = f2fma(n[i][2], w2, s_);
            s_ = f2fma(n[i][3], w3, s_);
            float lo, hi; upk(s_, lo, hi);
            float h1 = fmaxf(lo + hi + bb, 0.f);
            u64 hh = pk(h1, h1);
            acc[i][0] = f2fma(hh, m0, acc[i][0]);
            acc[i][1] = f2fma(hh, m1, acc[i][1]);
            acc[i][2] = f2fma(hh, m2, acc[i][2]);
            acc[i][3] = f2fma(hh, m3, acc[i][3]);
        }
    }

    float cz[8];
#pragma unroll
    for (int d = 0; d < 8; d++) cz[d] = g_c2[d];

    const float4* eap = (const float4*)edge_attr;
    float4* outp = (float4*)out;
#pragma unroll
    for (int i = 0; i < 4; i++) {
        int e = base + i;
        if (e >= E) break;
        float4 e0 = __ldg(eap + e * 2), e1 = __ldg(eap + e * 2 + 1);
        float x0, x1, x2, x3, x4, x5, x6, x7;
        upk(acc[i][0], x0, x1); upk(acc[i][1], x2, x3);
        upk(acc[i][2], x4, x5); upk(acc[i][3], x6, x7);
        float4 o0, o1;
        o0.x = e0.x + x0 + cz[0]; o0.y = e0.y + x1 + cz[1];
        o0.z = e0.z + x2 + cz[2]; o0.w = e0.w + x3 + cz[3];
        o1.x = e1.x + x4 + cz[4]; o1.y = e1.y + x5 + cz[5];
        o1.z = e1.z + x6 + cz[6]; o1.w = e1.w + x7 + cz[7];
        outp[e * 2] = o0; outp[e * 2 + 1] = o1;
    }
}

// ------------------------- launch ------------------------------------------
extern "C" void kernel_launch(void* const* d_in, const int* in_sizes, int n_in,
                              void* d_out, int out_size) {
    const float* edge_attr = (const float*)d_in[0];
    const float* nf        = (const float*)d_in[1];
    const int*   ei        = (const int*)  d_in[2];
    // d_in[3..8] = edge encoder params: dead code in the reference, unused.
    const float* nW1   = (const float*)d_in[9];
    const float* nb1   = (const float*)d_in[10];
    const float* ngam  = (const float*)d_in[11];
    const float* nbet  = (const float*)d_in[12];
    const float* nW2   = (const float*)d_in[13];
    const float* nb2   = (const float*)d_in[14];
    const float* Wv    = (const float*)d_in[15];
    const float* bv    = (const float*)d_in[16];
    const float* Wo    = (const float*)d_in[17];
    const float* bo    = (const float*)d_in[18];
    const float* Wp    = (const float*)d_in[19];
    const float* bp    = (const float*)d_in[20];
    (void)n_in; (void)out_size;

    int E = in_sizes[0] / DDIM;
    const int* ei0 = ei;
    const int* ei1 = ei + E;
    float* out = (float*)d_out;
    int fullE = (E / 16) * 16;

    // BN statistics via tensor cores (longest chain starts immediately)
    stats_kernel<<<SGRID, 256>>>(nf, ei0, ei1, nW1, nb1, fullE);

    // weight folding (grid-parallel, proven)
    fold_kernel<<<32, 256>>>(Wo, Wp, 0);    // R1 = Wo @ Wp
    fold_kernel<<<32, 256>>>(Wv, Wp, 1);    // R2 = Wv @ R1
    fold_kernel<<<32, 256>>>(nW2, Wp, 2);   // M  = nW2 @ R2

    // BN finalize: parallel partials reduce, then tiny pack kernel
    reduce_kernel<<<HDIM, 256>>>(ngam, nbet, nf, ei0, ei1, nW1, nb1, fullE, E);
    final_kernel<<<1, 256>>>(nb2, bv, bo, bp, Wp);

    // main fused pass, 4 edges / thread (exact R4 config)
    int gridB = (E + 1023) / 1024;
    main_kernel<<<gridB, 256>>>(edge_attr, nf, ei0, ei1, nW1, nb1, out, E);
}